// round 9
// baseline (speedup 1.0000x reference)
#include <cuda_runtime.h>

// ---------------------------------------------------------------------------
// BGATModel: B=262144 independent tiny graph-attention models.
// TWO threads per element (adjacent lanes): attention duplicated, fused
// LN+MLP1/MLP2 split across the pair by hidden-unit half; combined via shfl.
// ---------------------------------------------------------------------------

namespace {
constexpr int THREADS = 128;          // 64 elements per block
constexpr int PAIRS   = THREADS / 2;
constexpr float D_    = 50.0f;
constexpr float HZ_   = 5.0f;
constexpr float DMIN_ = 0.025f;
constexpr float PMAX_ = 1.0f;
constexpr float BMAX_ = 2.0f * 50.0f - 3.0f * 0.025f; // 99.925
constexpr float L2E_  = 1.4426950408889634f;
constexpr float AV6_  = 0.6f * 0.5f * L2E_;
constexpr float AV4_  = 0.4f * 0.5f * L2E_;

// shared float offsets
constexpr int CWU = 0;     // [d][k][c][h]   320
constexpr int CWA = 320;   //                320
constexpr int CWE = 640;   // [d][k][h]      160
constexpr int AV6 = 800;   // 160
constexpr int AV4 = 960;   // 160
constexpr int WRT = 1120;  // [d][c][i]      320 (Wres^T)
constexpr int WPU = 1440;  // [d][i][j] (w1*g)^T user  2560
constexpr int WPA = 4000;  //                  agent   2560
constexpr int SUN = 6560;  // [d][j] -sum_i w1g   80
constexpr int BUC = 6640;  // [d][j] b1+w1@lnb    80
constexpr int SAN = 6720;  constexpr int BAC = 6800;
constexpr int W2U = 6880;  // [d][j][2]          160
constexpr int W2A = 7040;
constexpr int B2U = 7200;  // 10 (pad 12)
constexpr int B2A = 7212;  // 10 (pad 12)
constexpr int RDW1 = 7224, RDB1 = 7256, RDW2 = 7264, RDB2 = 7296;
constexpr int RPW1 = 7300, RPB1 = 7332, RPW2 = 7340, RPB2 = 7372;
constexpr int WTOT = 7376;
}

typedef unsigned long long ull;
struct Ptrs { const float* a[28]; };

__device__ __forceinline__ ull pk2(float lo, float hi) {
    ull r; asm("mov.b64 %0,{%1,%2};" : "=l"(r) : "f"(lo), "f"(hi)); return r;
}
__device__ __forceinline__ void upk2(ull v, float& lo, float& hi) {
    asm("mov.b64 {%0,%1},%2;" : "=f"(lo), "=f"(hi) : "l"(v));
}
__device__ __forceinline__ ull dupf(float x) { return pk2(x, x); }
__device__ __forceinline__ ull f2fma(ull a, ull b, ull c) {
    ull r; asm("fma.rn.f32x2 %0,%1,%2,%3;" : "=l"(r) : "l"(a), "l"(b), "l"(c)); return r;
}
__device__ __forceinline__ ull f2mul(ull a, ull b) {
    ull r; asm("mul.rn.f32x2 %0,%1,%2;" : "=l"(r) : "l"(a), "l"(b)); return r;
}
__device__ __forceinline__ ull f2add(ull a, ull b) {
    ull r; asm("add.rn.f32x2 %0,%1,%2;" : "=l"(r) : "l"(a), "l"(b)); return r;
}
__device__ __forceinline__ float ex2(float x) {
    float r; asm("ex2.approx.f32 %0,%1;" : "=f"(r) : "f"(x)); return r;
}
// pairwise (xor-1) sum of a packed f32x2, via two 32-bit shuffles
__device__ __forceinline__ ull pair_sum(ull v) {
    float lo, hi; upk2(v, lo, hi);
    float plo = __shfl_xor_sync(0xFFFFFFFFu, lo, 1);
    float phi = __shfl_xor_sync(0xFFFFFFFFu, hi, 1);
    return f2add(v, pk2(plo, phi));
}

__global__ __launch_bounds__(THREADS, 3)
void bgat_kernel(Ptrs p, float* __restrict__ out, int B) {
    __shared__ float sW[WTOT];

    // ---------------- staging + weight precompute ----------------
    {
        const int t = threadIdx.x;
        for (int x = t; x < 320; x += THREADS) {
            int d = x >> 6, k = (x >> 3) & 7, h = (x >> 1) & 3, c = x & 1;
            sW[CWU + (d * 8 + k) * 8 + c * 4 + h] = p.a[3][x];
            sW[CWA + (d * 8 + k) * 8 + c * 4 + h] = p.a[4][x];
        }
        for (int x = t; x < 160; x += THREADS) {
            sW[CWE + x] = p.a[5][x];
            sW[AV6 + x] = p.a[6][x] * AV6_;
            sW[AV4 + x] = p.a[6][x] * AV4_;
        }
        for (int x = t; x < 320; x += THREADS) {
            int d = x >> 6, i = (x >> 1) & 31, c = x & 1;
            sW[WRT + (d * 2 + c) * 32 + i] = p.a[7][x];
        }
        for (int x = t; x < 2560; x += THREADS) {
            int d = x >> 9, j = (x >> 5) & 15, i = x & 31;
            sW[WPU + (d * 32 + i) * 16 + j] = p.a[12][x] * p.a[8][d * 32 + i];
            sW[WPA + (d * 32 + i) * 16 + j] = p.a[16][x] * p.a[10][d * 32 + i];
        }
        for (int x = t; x < 80; x += THREADS) {
            int d = x >> 4, j = x & 15;
            float su = 0.f, bu = 0.f, sa = 0.f, ba = 0.f;
            for (int i = 0; i < 32; i++) {
                float wu_ = p.a[12][(d * 16 + j) * 32 + i];
                float wa_ = p.a[16][(d * 16 + j) * 32 + i];
                su += wu_ * p.a[8][d * 32 + i];  bu += wu_ * p.a[9][d * 32 + i];
                sa += wa_ * p.a[10][d * 32 + i]; ba += wa_ * p.a[11][d * 32 + i];
            }
            sW[SUN + x] = -su; sW[BUC + x] = p.a[13][x] + bu;
            sW[SAN + x] = -sa; sW[BAC + x] = p.a[17][x] + ba;
        }
        for (int x = t; x < 160; x += THREADS) {
            int d = x >> 5, j = (x >> 1) & 15, c = x & 1;
            sW[W2U + d * 32 + j * 2 + c] = p.a[14][(d * 2 + c) * 16 + j];
            sW[W2A + d * 32 + j * 2 + c] = p.a[18][(d * 2 + c) * 16 + j];
        }
        for (int x = t; x < 10; x += THREADS) {
            int d = x >> 1, c = x & 1;
            sW[B2U + d * 2 + c] = p.a[15][x];
            sW[B2A + d * 2 + c] = p.a[19][x];
        }
        for (int x = t; x < 32; x += THREADS) {
            sW[RDW1 + x] = p.a[20][x]; sW[RDW2 + x] = p.a[22][x];
            sW[RPW1 + x] = p.a[24][x]; sW[RPW2 + x] = p.a[26][x];
        }
        for (int x = t; x < 8; x += THREADS) { sW[RDB1 + x] = p.a[21][x]; sW[RPB1 + x] = p.a[25][x]; }
        for (int x = t; x < 4; x += THREADS) { sW[RDB2 + x] = p.a[23][x]; sW[RPB2 + x] = p.a[27][x]; }
    }
    __syncthreads();

    const int s = threadIdx.x & 1;                  // hidden-half owner
    const int pair = blockIdx.x * PAIRS + (threadIdx.x >> 1);
    const int b = (pair < B) ? pair : (B - 1);      // clamp; keep all lanes alive
    const int so8  = s * 8;                         // float offset for j-half
    const int so16 = s * 16;

    float uf[2][2], af[4][2];
    {
        float4 uv = ((const float4*)p.a[0])[b];
        uf[0][0] = uv.x; uf[0][1] = uv.y; uf[1][0] = uv.z; uf[1][1] = uv.w;
        float4 dv = ((const float4*)p.a[1])[b];
        float4 pv = ((const float4*)p.a[2])[b];
        af[0][0] = pv.x; af[0][1] = dv.x; af[1][0] = pv.y; af[1][1] = dv.y;
        af[2][0] = pv.z; af[2][1] = dv.z; af[3][0] = pv.w; af[3][1] = dv.w;
    }

#pragma unroll 1
    for (int d = 0; d < 5; d++) {
        float da[4], xpos[4], sd = 1e-6f;
#pragma unroll
        for (int n = 0; n < 4; n++) { da[n] = fmaxf(af[n][1], 0.f); sd += da[n]; }
        float inv_sd = BMAX_ / fmaxf(sd, 1e-6f);
        { float cum = 0.f;
#pragma unroll
          for (int n = 0; n < 4; n++) { cum += da[n] * inv_sd; xpos[n] = cum - D_ + DMIN_ * (float)n; } }

        ull dedg[2][4];
#pragma unroll
        for (int m = 0; m < 2; m++)
#pragma unroll
            for (int n = 0; n < 4; n++) {
                float dx = uf[m][0] - xpos[n], dy = uf[m][1];
                dedg[m][n] = dupf(sqrtf(fmaf(dx, dx, dy * dy)));
            }

        ull duf0[2], duf1[2], daf0[4], daf1[4];
#pragma unroll
        for (int m = 0; m < 2; m++) { duf0[m] = dupf(uf[m][0]); duf1[m] = dupf(uf[m][1]); }
#pragma unroll
        for (int n = 0; n < 4; n++) { daf0[n] = dupf(af[n][0]); daf1[n] = dupf(af[n][1]); }

        // half-width MLP1 accumulators (this thread's 8 hidden units as 4 ull)
        ull uacc[2][4], aacc[4][4];
        ull usum[2], usq[2], asum[4], asq[4];
#pragma unroll
        for (int m = 0; m < 2; m++) {
            usum[m] = 0ull; usq[m] = 0ull;
#pragma unroll
            for (int j = 0; j < 4; j++) uacc[m][j] = 0ull;
        }
#pragma unroll
        for (int n = 0; n < 4; n++) {
            asum[n] = 0ull; asq[n] = 0ull;
#pragma unroll
            for (int j = 0; j < 4; j++) aacc[n][j] = 0ull;
        }

#pragma unroll 2
        for (int k = 0; k < 8; k++) {
            const ull* wu2 = (const ull*)&sW[CWU + (d * 8 + k) * 8];
            const ull* wa2 = (const ull*)&sW[CWA + (d * 8 + k) * 8];
            const ull* we2 = (const ull*)&sW[CWE + (d * 8 + k) * 4];
            float4 a6 = *(const float4*)&sW[AV6 + (d * 8 + k) * 4];
            float4 a4 = *(const float4*)&sW[AV4 + (d * 8 + k) * 4];

            ull U2[2][2], A2[4][2];
#pragma unroll
            for (int m = 0; m < 2; m++) {
                U2[m][0] = f2fma(duf0[m], wu2[0], f2mul(duf1[m], wu2[2]));
                U2[m][1] = f2fma(duf0[m], wu2[1], f2mul(duf1[m], wu2[3]));
            }
#pragma unroll
            for (int n = 0; n < 4; n++) {
                A2[n][0] = f2fma(daf0[n], wa2[0], f2mul(daf1[n], wa2[2]));
                A2[n][1] = f2fma(daf0[n], wa2[1], f2mul(daf1[n], wa2[3]));
            }

            float alpha[2][4];
#pragma unroll
            for (int m = 0; m < 2; m++) {
                float sc[4];
#pragma unroll
                for (int n = 0; n < 4; n++) {
                    ull s0 = f2fma(dedg[m][n], we2[0], f2add(U2[m][0], A2[n][0]));
                    ull s1 = f2fma(dedg[m][n], we2[1], f2add(U2[m][1], A2[n][1]));
                    float t0, t1, t2, t3;
                    upk2(s0, t0, t1); upk2(s1, t2, t3);
                    float pa = fmaf(t0, a6.x, fmaf(t1, a6.y, fmaf(t2, a6.z, t3 * a6.w)));
                    float pb = fmaf(fabsf(t0), a4.x, fmaf(fabsf(t1), a4.y,
                               fmaf(fabsf(t2), a4.z, fabsf(t3) * a4.w)));
                    sc[n] = pa + pb;
                }
                float mx = fmaxf(fmaxf(sc[0], sc[1]), fmaxf(sc[2], sc[3]));
                float e0 = ex2(sc[0] - mx), e1 = ex2(sc[1] - mx);
                float e2 = ex2(sc[2] - mx), e3 = ex2(sc[3] - mx);
                float rs = __frcp_rn(((e0 + e1) + (e2 + e3)));
                alpha[m][0] = e0 * rs; alpha[m][1] = e1 * rs;
                alpha[m][2] = e2 * rs; alpha[m][3] = e3 * rs;
            }
            ull dal[2][4];
#pragma unroll
            for (int m = 0; m < 2; m++)
#pragma unroll
                for (int n = 0; n < 4; n++) dal[m][n] = dupf(alpha[m][n]);

#pragma unroll
            for (int pp = 0; pp < 2; pp++) {
                ull wres0 = *(const ull*)&sW[WRT + (d * 2 + 0) * 32 + k * 4 + pp * 2];
                ull wres1 = *(const ull*)&sW[WRT + (d * 2 + 1) * 32 + k * 4 + pp * 2];
                ull u2[2], v2[4];
#pragma unroll
                for (int m = 0; m < 2; m++)
                    u2[m] = f2fma(duf0[m], wres0, f2mul(duf1[m], wres1));
#pragma unroll
                for (int n = 0; n < 4; n++) {
                    ull e0 = f2mul(dedg[0][n], we2[pp]);
                    u2[0] = f2fma(f2add(A2[n][pp], e0), dal[0][n], u2[0]);
                    ull ue0 = f2add(U2[0][pp], e0);
                    ull e1 = f2mul(dedg[1][n], we2[pp]);
                    u2[1] = f2fma(f2add(A2[n][pp], e1), dal[1][n], u2[1]);
                    ull ue1 = f2add(U2[1][pp], e1);
                    v2[n] = f2fma(ue1, dal[1][n], f2mul(ue0, dal[0][n]));
                }
#pragma unroll
                for (int m = 0; m < 2; m++) {
                    usum[m] = f2add(usum[m], u2[m]);
                    usq[m]  = f2fma(u2[m], u2[m], usq[m]);
                }
#pragma unroll
                for (int n = 0; n < 4; n++) {
                    asum[n] = f2add(asum[n], v2[n]);
                    asq[n]  = f2fma(v2[n], v2[n], asq[n]);
                }
                float ul[2][2], vl[4][2];
#pragma unroll
                for (int m = 0; m < 2; m++) upk2(u2[m], ul[m][0], ul[m][1]);
#pragma unroll
                for (int n = 0; n < 4; n++) upk2(v2[n], vl[n][0], vl[n][1]);

#pragma unroll
                for (int ln = 0; ln < 2; ln++) {
                    const int i = k * 4 + pp * 2 + ln;
                    const ulonglong2* ru = (const ulonglong2*)&sW[WPU + (d * 32 + i) * 16 + so8];
                    ulonglong2 r0 = ru[0], r1 = ru[1];
#pragma unroll
                    for (int m = 0; m < 2; m++) {
                        ull du = dupf(ul[m][ln]);
                        uacc[m][0] = f2fma(du, r0.x, uacc[m][0]);
                        uacc[m][1] = f2fma(du, r0.y, uacc[m][1]);
                        uacc[m][2] = f2fma(du, r1.x, uacc[m][2]);
                        uacc[m][3] = f2fma(du, r1.y, uacc[m][3]);
                    }
                    const ulonglong2* ra = (const ulonglong2*)&sW[WPA + (d * 32 + i) * 16 + so8];
                    ulonglong2 q0 = ra[0], q1 = ra[1];
#pragma unroll
                    for (int n = 0; n < 4; n++) {
                        ull dv = dupf(vl[n][ln]);
                        aacc[n][0] = f2fma(dv, q0.x, aacc[n][0]);
                        aacc[n][1] = f2fma(dv, q0.y, aacc[n][1]);
                        aacc[n][2] = f2fma(dv, q1.x, aacc[n][2]);
                        aacc[n][3] = f2fma(dv, q1.y, aacc[n][3]);
                    }
                }
            }
        }

        // -------- epilogue: LN + half-MLP per instance, combine across pair --------
        {
            const ull* sn = (const ull*)&sW[SUN + d * 16 + so8];
            const ull* bc = (const ull*)&sW[BUC + d * 16 + so8];
            const ull* w2 = (const ull*)&sW[W2U + d * 32 + so16];
            ull b2 = s ? 0ull : *(const ull*)&sW[B2U + d * 2];
#pragma unroll
            for (int m = 0; m < 2; m++) {
                float s0, s1, q0, q1;
                upk2(usum[m], s0, s1); upk2(usq[m], q0, q1);
                float mu = (s0 + s1) * (1.0f / 32.0f);
                float var = (q0 + q1) * (1.0f / 32.0f) - mu * mu;
                float rr = rsqrtf(var + 1e-5f);
                ull dmu = dupf(mu), drr = dupf(rr);
                ull o2 = b2;
#pragma unroll
                for (int jp = 0; jp < 4; jp++) {
                    ull t2 = f2fma(dmu, sn[jp], uacc[m][jp]);
                    ull c2 = f2fma(drr, t2, bc[jp]);
                    float c0, c1; upk2(c2, c0, c1);
                    c0 = fmaxf(c0, 0.f); c1 = fmaxf(c1, 0.f);
                    o2 = f2fma(dupf(c0), w2[2 * jp], o2);
                    o2 = f2fma(dupf(c1), w2[2 * jp + 1], o2);
                }
                o2 = pair_sum(o2);
                upk2(o2, uf[m][0], uf[m][1]);
            }
        }
        {
            const ull* sn = (const ull*)&sW[SAN + d * 16 + so8];
            const ull* bc = (const ull*)&sW[BAC + d * 16 + so8];
            const ull* w2 = (const ull*)&sW[W2A + d * 32 + so16];
            ull b2 = s ? 0ull : *(const ull*)&sW[B2A + d * 2];
#pragma unroll
            for (int n = 0; n < 4; n++) {
                float s0, s1, q0, q1;
                upk2(asum[n], s0, s1); upk2(asq[n], q0, q1);
                float mu = (s0 + s1) * (1.0f / 32.0f);
                float var = (q0 + q1) * (1.0f / 32.0f) - mu * mu;
                float rr = rsqrtf(var + 1e-5f);
                ull dmu = dupf(mu), drr = dupf(rr);
                ull o2 = b2;
#pragma unroll
                for (int jp = 0; jp < 4; jp++) {
                    ull t2 = f2fma(dmu, sn[jp], aacc[n][jp]);
                    ull c2 = f2fma(drr, t2, bc[jp]);
                    float c0, c1; upk2(c2, c0, c1);
                    c0 = fmaxf(c0, 0.f); c1 = fmaxf(c1, 0.f);
                    o2 = f2fma(dupf(c0), w2[2 * jp], o2);
                    o2 = f2fma(dupf(c1), w2[2 * jp + 1], o2);
                }
                o2 = pair_sum(o2);
                upk2(o2, af[n][0], af[n][1]);
            }
        }
    }

    // ---------------- readout heads (both lanes compute; writes split) ----------------
    float td[8];
#pragma unroll
    for (int i = 0; i < 8; i++) {
        float acc = sW[RDB1 + i];
#pragma unroll
        for (int n = 0; n < 4; n++) acc = fmaf(af[n][1], sW[RDW1 + i * 4 + n], acc);
        td[i] = fmaxf(acc, 0.f);
    }
    float daux[4], sumd = 0.f;
#pragma unroll
    for (int j = 0; j < 4; j++) {
        float acc = sW[RDB2 + j];
#pragma unroll
        for (int i = 0; i < 8; i++) acc = fmaf(td[i], sW[RDW2 + j * 8 + i], acc);
        daux[j] = fmaxf(acc, 0.001f);
        sumd += daux[j];
    }
    float fd = BMAX_ / sumd;
    float sdelta[4], x[4];
    { float cum = 0.f;
#pragma unroll
      for (int n = 0; n < 4; n++) {
          sdelta[n] = daux[n] * fd;
          cum += sdelta[n];
          x[n] = cum + DMIN_ * (float)n - D_ * (float)(n + 1);
      } }

    float tp[8];
#pragma unroll
    for (int i = 0; i < 8; i++) {
        float acc = sW[RPB1 + i];
#pragma unroll
        for (int n = 0; n < 4; n++) acc = fmaf(af[n][0], sW[RPW1 + i * 4 + n], acc);
        tp[i] = fmaxf(acc, 0.f);
    }
    float paux[4], sump = 1e-6f;
#pragma unroll
    for (int j = 0; j < 4; j++) {
        float acc = sW[RPB2 + j];
#pragma unroll
        for (int i = 0; i < 8; i++) acc = fmaf(tp[i], sW[RPW2 + j * 8 + i], acc);
        paux[j] = fmaxf(acc, 0.001f);
        sump += paux[j];
    }
    float fp = PMAX_ / fmaxf(PMAX_, sump);

    if (pair < B) {
        if (s == 0) {
            ((float4*)out)[b] = make_float4(paux[0] * fp, paux[1] * fp, paux[2] * fp, paux[3] * fp);
            ((float4*)(out + 4 * (size_t)B))[b] = make_float4(sdelta[0], sdelta[1], sdelta[2], sdelta[3]);
        } else {
            float* op = out + 8 * (size_t)B + (size_t)b * 12;
            ((float4*)op)[0] = make_float4(x[0], 0.f, HZ_, x[1]);
            ((float4*)op)[1] = make_float4(0.f, HZ_, x[2], 0.f);
            ((float4*)op)[2] = make_float4(HZ_, x[3], 0.f, HZ_);
        }
    }
}

extern "C" void kernel_launch(void* const* d_in, const int* in_sizes, int n_in,
                              void* d_out, int out_size) {
    Ptrs p;
    for (int i = 0; i < 28; i++) p.a[i] = (const float*)d_in[i];
    int B = in_sizes[0] / 4;
    int grid = (B + PAIRS - 1) / PAIRS;
    bgat_kernel<<<grid, THREADS>>>(p, (float*)d_out, B);
}

// round 11
// speedup vs baseline: 1.6031x; 1.6031x over previous
#include <cuda_runtime.h>

// ---------------------------------------------------------------------------
// BGATModel: B=262144 independent tiny graph-attention models.
// One thread per element; LN+MLP1 fused into attention loop; fma.rn.f32x2;
// leaky_relu folded as 0.6x+0.4|x| into pre-scaled attention vectors.
// (R3 structure + fold, unroll 2, dual-accumulator epilogue.)
// ---------------------------------------------------------------------------

namespace {
constexpr int THREADS = 64;
constexpr float D_    = 50.0f;
constexpr float HZ_   = 5.0f;
constexpr float DMIN_ = 0.025f;
constexpr float PMAX_ = 1.0f;
constexpr float BMAX_ = 2.0f * 50.0f - 3.0f * 0.025f; // 99.925
constexpr float L2E_  = 1.4426950408889634f;
constexpr float AV6_  = 0.6f * 0.5f * L2E_;   // leaky pos part * SCALE * log2e
constexpr float AV4_  = 0.4f * 0.5f * L2E_;   // leaky abs part * SCALE * log2e

// shared float offsets
constexpr int CWU = 0;     // [d][k][c][h]   320
constexpr int CWA = 320;   //                320
constexpr int CWE = 640;   // [d][k][h]      160
constexpr int AV6 = 800;   // 160
constexpr int AV4 = 960;   // 160
constexpr int WRT = 1120;  // [d][c][i]      320 (Wres^T)
constexpr int WPU = 1440;  // [d][i][j] (w1*g)^T user  2560
constexpr int WPA = 4000;  //                  agent   2560
constexpr int SUN = 6560;  // [d][j] -sum_i w1g   80
constexpr int BUC = 6640;  // [d][j] b1+w1@lnb    80
constexpr int SAN = 6720;  constexpr int BAC = 6800;
constexpr int W2U = 6880;  // [d][j][2]          160
constexpr int W2A = 7040;
constexpr int B2U = 7200;  // 10 (pad 12)
constexpr int B2A = 7212;  // 10 (pad 12)
constexpr int RDW1 = 7224, RDB1 = 7256, RDW2 = 7264, RDB2 = 7296;
constexpr int RPW1 = 7300, RPB1 = 7332, RPW2 = 7340, RPB2 = 7372;
constexpr int WTOT = 7376;
}

typedef unsigned long long ull;
struct Ptrs { const float* a[28]; };

__device__ __forceinline__ ull pk2(float lo, float hi) {
    ull r; asm("mov.b64 %0,{%1,%2};" : "=l"(r) : "f"(lo), "f"(hi)); return r;
}
__device__ __forceinline__ void upk2(ull v, float& lo, float& hi) {
    asm("mov.b64 {%0,%1},%2;" : "=f"(lo), "=f"(hi) : "l"(v));
}
__device__ __forceinline__ ull dupf(float x) { return pk2(x, x); }
__device__ __forceinline__ ull f2fma(ull a, ull b, ull c) {
    ull r; asm("fma.rn.f32x2 %0,%1,%2,%3;" : "=l"(r) : "l"(a), "l"(b), "l"(c)); return r;
}
__device__ __forceinline__ ull f2mul(ull a, ull b) {
    ull r; asm("mul.rn.f32x2 %0,%1,%2;" : "=l"(r) : "l"(a), "l"(b)); return r;
}
__device__ __forceinline__ ull f2add(ull a, ull b) {
    ull r; asm("add.rn.f32x2 %0,%1,%2;" : "=l"(r) : "l"(a), "l"(b)); return r;
}
__device__ __forceinline__ float ex2(float x) {
    float r; asm("ex2.approx.f32 %0,%1;" : "=f"(r) : "f"(x)); return r;
}

__global__ __launch_bounds__(THREADS, 6)
void bgat_kernel(Ptrs p, float* __restrict__ out, int B) {
    __shared__ float sW[WTOT];

    // ---------------- staging + weight precompute ----------------
    {
        const int t = threadIdx.x;
        for (int x = t; x < 320; x += THREADS) {
            int d = x >> 6, k = (x >> 3) & 7, h = (x >> 1) & 3, c = x & 1;
            sW[CWU + (d * 8 + k) * 8 + c * 4 + h] = p.a[3][x];
            sW[CWA + (d * 8 + k) * 8 + c * 4 + h] = p.a[4][x];
        }
        for (int x = t; x < 160; x += THREADS) {
            sW[CWE + x] = p.a[5][x];
            sW[AV6 + x] = p.a[6][x] * AV6_;
            sW[AV4 + x] = p.a[6][x] * AV4_;
        }
        for (int x = t; x < 320; x += THREADS) {
            int d = x >> 6, i = (x >> 1) & 31, c = x & 1;
            sW[WRT + (d * 2 + c) * 32 + i] = p.a[7][x];
        }
        for (int x = t; x < 2560; x += THREADS) {
            int d = x >> 9, j = (x >> 5) & 15, i = x & 31;
            sW[WPU + (d * 32 + i) * 16 + j] = p.a[12][x] * p.a[8][d * 32 + i];
            sW[WPA + (d * 32 + i) * 16 + j] = p.a[16][x] * p.a[10][d * 32 + i];
        }
        for (int x = t; x < 80; x += THREADS) {
            int d = x >> 4, j = x & 15;
            float su = 0.f, bu = 0.f, sa = 0.f, ba = 0.f;
            for (int i = 0; i < 32; i++) {
                float wu_ = p.a[12][(d * 16 + j) * 32 + i];
                float wa_ = p.a[16][(d * 16 + j) * 32 + i];
                su += wu_ * p.a[8][d * 32 + i];  bu += wu_ * p.a[9][d * 32 + i];
                sa += wa_ * p.a[10][d * 32 + i]; ba += wa_ * p.a[11][d * 32 + i];
            }
            sW[SUN + x] = -su; sW[BUC + x] = p.a[13][x] + bu;
            sW[SAN + x] = -sa; sW[BAC + x] = p.a[17][x] + ba;
        }
        for (int x = t; x < 160; x += THREADS) {
            int d = x >> 5, j = (x >> 1) & 15, c = x & 1;
            sW[W2U + d * 32 + j * 2 + c] = p.a[14][(d * 2 + c) * 16 + j];
            sW[W2A + d * 32 + j * 2 + c] = p.a[18][(d * 2 + c) * 16 + j];
        }
        for (int x = t; x < 10; x += THREADS) {
            int d = x >> 1, c = x & 1;
            sW[B2U + d * 2 + c] = p.a[15][x];
            sW[B2A + d * 2 + c] = p.a[19][x];
        }
        for (int x = t; x < 32; x += THREADS) {
            sW[RDW1 + x] = p.a[20][x]; sW[RDW2 + x] = p.a[22][x];
            sW[RPW1 + x] = p.a[24][x]; sW[RPW2 + x] = p.a[26][x];
        }
        for (int x = t; x < 8; x += THREADS) { sW[RDB1 + x] = p.a[21][x]; sW[RPB1 + x] = p.a[25][x]; }
        for (int x = t; x < 4; x += THREADS) { sW[RDB2 + x] = p.a[23][x]; sW[RPB2 + x] = p.a[27][x]; }
    }
    __syncthreads();

    const int b = blockIdx.x * THREADS + threadIdx.x;
    if (b >= B) return;

    float uf[2][2], af[4][2];
    {
        float4 uv = ((const float4*)p.a[0])[b];
        uf[0][0] = uv.x; uf[0][1] = uv.y; uf[1][0] = uv.z; uf[1][1] = uv.w;
        float4 dv = ((const float4*)p.a[1])[b];
        float4 pv = ((const float4*)p.a[2])[b];
        af[0][0] = pv.x; af[0][1] = dv.x; af[1][0] = pv.y; af[1][1] = dv.y;
        af[2][0] = pv.z; af[2][1] = dv.z; af[3][0] = pv.w; af[3][1] = dv.w;
    }

#pragma unroll 1
    for (int d = 0; d < 5; d++) {
        float da[4], xpos[4], sd = 1e-6f;
#pragma unroll
        for (int n = 0; n < 4; n++) { da[n] = fmaxf(af[n][1], 0.f); sd += da[n]; }
        float inv_sd = BMAX_ / fmaxf(sd, 1e-6f);
        { float cum = 0.f;
#pragma unroll
          for (int n = 0; n < 4; n++) { cum += da[n] * inv_sd; xpos[n] = cum - D_ + DMIN_ * (float)n; } }

        ull dedg[2][4];
#pragma unroll
        for (int m = 0; m < 2; m++)
#pragma unroll
            for (int n = 0; n < 4; n++) {
                float dx = uf[m][0] - xpos[n], dy = uf[m][1];
                dedg[m][n] = dupf(sqrtf(fmaf(dx, dx, dy * dy)));
            }

        ull duf0[2], duf1[2], daf0[4], daf1[4];
#pragma unroll
        for (int m = 0; m < 2; m++) { duf0[m] = dupf(uf[m][0]); duf1[m] = dupf(uf[m][1]); }
#pragma unroll
        for (int n = 0; n < 4; n++) { daf0[n] = dupf(af[n][0]); daf1[n] = dupf(af[n][1]); }

        ull uacc[2][8], aacc[4][8];
        ull usum[2], usq[2], asum[4], asq[4];
#pragma unroll
        for (int m = 0; m < 2; m++) {
            usum[m] = 0ull; usq[m] = 0ull;
#pragma unroll
            for (int j = 0; j < 8; j++) uacc[m][j] = 0ull;
        }
#pragma unroll
        for (int n = 0; n < 4; n++) {
            asum[n] = 0ull; asq[n] = 0ull;
#pragma unroll
            for (int j = 0; j < 8; j++) aacc[n][j] = 0ull;
        }

#pragma unroll 2
        for (int k = 0; k < 8; k++) {
            const ull* wu2 = (const ull*)&sW[CWU + (d * 8 + k) * 8];
            const ull* wa2 = (const ull*)&sW[CWA + (d * 8 + k) * 8];
            const ull* we2 = (const ull*)&sW[CWE + (d * 8 + k) * 4];
            float4 a6 = *(const float4*)&sW[AV6 + (d * 8 + k) * 4];
            float4 a4 = *(const float4*)&sW[AV4 + (d * 8 + k) * 4];

            ull U2[2][2], A2[4][2];
#pragma unroll
            for (int m = 0; m < 2; m++) {
                U2[m][0] = f2fma(duf0[m], wu2[0], f2mul(duf1[m], wu2[2]));
                U2[m][1] = f2fma(duf0[m], wu2[1], f2mul(duf1[m], wu2[3]));
            }
#pragma unroll
            for (int n = 0; n < 4; n++) {
                A2[n][0] = f2fma(daf0[n], wa2[0], f2mul(daf1[n], wa2[2]));
                A2[n][1] = f2fma(daf0[n], wa2[1], f2mul(daf1[n], wa2[3]));
            }

            // scores (exp2 domain, leaky folded via |t|) + softmax
            float alpha[2][4];
#pragma unroll
            for (int m = 0; m < 2; m++) {
                float sc[4];
#pragma unroll
                for (int n = 0; n < 4; n++) {
                    ull s0 = f2fma(dedg[m][n], we2[0], f2add(U2[m][0], A2[n][0]));
                    ull s1 = f2fma(dedg[m][n], we2[1], f2add(U2[m][1], A2[n][1]));
                    float t0, t1, t2, t3;
                    upk2(s0, t0, t1); upk2(s1, t2, t3);
                    float pa = fmaf(t0, a6.x, fmaf(t1, a6.y, fmaf(t2, a6.z, t3 * a6.w)));
                    float pb = fmaf(fabsf(t0), a4.x, fmaf(fabsf(t1), a4.y,
                               fmaf(fabsf(t2), a4.z, fabsf(t3) * a4.w)));
                    sc[n] = pa + pb;
                }
                float mx = fmaxf(fmaxf(sc[0], sc[1]), fmaxf(sc[2], sc[3]));
                float e0 = ex2(sc[0] - mx), e1 = ex2(sc[1] - mx);
                float e2 = ex2(sc[2] - mx), e3 = ex2(sc[3] - mx);
                float rs = __fdividef(1.0f, (e0 + e1) + (e2 + e3));
                alpha[m][0] = e0 * rs; alpha[m][1] = e1 * rs;
                alpha[m][2] = e2 * rs; alpha[m][3] = e3 * rs;
            }
            ull dal[2][4];
#pragma unroll
            for (int m = 0; m < 2; m++)
#pragma unroll
                for (int n = 0; n < 4; n++) dal[m][n] = dupf(alpha[m][n]);

#pragma unroll
            for (int pp = 0; pp < 2; pp++) {
                ull wres0 = *(const ull*)&sW[WRT + (d * 2 + 0) * 32 + k * 4 + pp * 2];
                ull wres1 = *(const ull*)&sW[WRT + (d * 2 + 1) * 32 + k * 4 + pp * 2];
                ull u2[2], v2[4];
#pragma unroll
                for (int m = 0; m < 2; m++)
                    u2[m] = f2fma(duf0[m], wres0, f2mul(duf1[m], wres1));
#pragma unroll
                for (int n = 0; n < 4; n++) {
                    ull e0 = f2mul(dedg[0][n], we2[pp]);
                    u2[0] = f2fma(f2add(A2[n][pp], e0), dal[0][n], u2[0]);
                    ull ue0 = f2add(U2[0][pp], e0);
                    ull e1 = f2mul(dedg[1][n], we2[pp]);
                    u2[1] = f2fma(f2add(A2[n][pp], e1), dal[1][n], u2[1]);
                    ull ue1 = f2add(U2[1][pp], e1);
                    v2[n] = f2fma(ue1, dal[1][n], f2mul(ue0, dal[0][n]));
                }
#pragma unroll
                for (int m = 0; m < 2; m++) {
                    usum[m] = f2add(usum[m], u2[m]);
                    usq[m]  = f2fma(u2[m], u2[m], usq[m]);
                }
#pragma unroll
                for (int n = 0; n < 4; n++) {
                    asum[n] = f2add(asum[n], v2[n]);
                    asq[n]  = f2fma(v2[n], v2[n], asq[n]);
                }
                float ul[2][2], vl[4][2];
#pragma unroll
                for (int m = 0; m < 2; m++) upk2(u2[m], ul[m][0], ul[m][1]);
#pragma unroll
                for (int n = 0; n < 4; n++) upk2(v2[n], vl[n][0], vl[n][1]);

#pragma unroll
                for (int ln = 0; ln < 2; ln++) {
                    const int i = k * 4 + pp * 2 + ln;
                    const ulonglong2* ru = (const ulonglong2*)&sW[WPU + (d * 32 + i) * 16];
                    ulonglong2 r0 = ru[0], r1 = ru[1], r2 = ru[2], r3 = ru[3];
#pragma unroll
                    for (int m = 0; m < 2; m++) {
                        ull du = dupf(ul[m][ln]);
                        uacc[m][0] = f2fma(du, r0.x, uacc[m][0]);
                        uacc[m][1] = f2fma(du, r0.y, uacc[m][1]);
                        uacc[m][2] = f2fma(du, r1.x, uacc[m][2]);
                        uacc[m][3] = f2fma(du, r1.y, uacc[m][3]);
                        uacc[m][4] = f2fma(du, r2.x, uacc[m][4]);
                        uacc[m][5] = f2fma(du, r2.y, uacc[m][5]);
                        uacc[m][6] = f2fma(du, r3.x, uacc[m][6]);
                        uacc[m][7] = f2fma(du, r3.y, uacc[m][7]);
                    }
                    const ulonglong2* ra = (const ulonglong2*)&sW[WPA + (d * 32 + i) * 16];
                    ulonglong2 q0 = ra[0], q1 = ra[1], q2 = ra[2], q3 = ra[3];
#pragma unroll
                    for (int n = 0; n < 4; n++) {
                        ull dv = dupf(vl[n][ln]);
                        aacc[n][0] = f2fma(dv, q0.x, aacc[n][0]);
                        aacc[n][1] = f2fma(dv, q0.y, aacc[n][1]);
                        aacc[n][2] = f2fma(dv, q1.x, aacc[n][2]);
                        aacc[n][3] = f2fma(dv, q1.y, aacc[n][3]);
                        aacc[n][4] = f2fma(dv, q2.x, aacc[n][4]);
                        aacc[n][5] = f2fma(dv, q2.y, aacc[n][5]);
                        aacc[n][6] = f2fma(dv, q3.x, aacc[n][6]);
                        aacc[n][7] = f2fma(dv, q3.y, aacc[n][7]);
                    }
                }
            }
        }

        // -------- epilogue: finish LN + MLP per instance (dual accumulators) --------
        float ufn[2][2], afn[4][2];
        {
            const ull* sn = (const ull*)&sW[SUN + d * 16];
            const ull* bc = (const ull*)&sW[BUC + d * 16];
            const ull* w2 = (const ull*)&sW[W2U + d * 32];
            ull b2 = *(const ull*)&sW[B2U + d * 2];
#pragma unroll
            for (int m = 0; m < 2; m++) {
                float s0, s1, q0, q1;
                upk2(usum[m], s0, s1); upk2(usq[m], q0, q1);
                float mu = (s0 + s1) * (1.0f / 32.0f);
                float var = (q0 + q1) * (1.0f / 32.0f) - mu * mu;
                float rr = rsqrtf(var + 1e-5f);
                ull dmu = dupf(mu), drr = dupf(rr);
                ull o2a = b2, o2b = 0ull;
#pragma unroll
                for (int jp = 0; jp < 8; jp++) {
                    ull t2 = f2fma(dmu, sn[jp], uacc[m][jp]);
                    ull c2 = f2fma(drr, t2, bc[jp]);
                    float c0, c1; upk2(c2, c0, c1);
                    c0 = fmaxf(c0, 0.f); c1 = fmaxf(c1, 0.f);
                    o2a = f2fma(dupf(c0), w2[2 * jp], o2a);
                    o2b = f2fma(dupf(c1), w2[2 * jp + 1], o2b);
                }
                upk2(f2add(o2a, o2b), ufn[m][0], ufn[m][1]);
            }
        }
        {
            const ull* sn = (const ull*)&sW[SAN + d * 16];
            const ull* bc = (const ull*)&sW[BAC + d * 16];
            const ull* w2 = (const ull*)&sW[W2A + d * 32];
            ull b2 = *(const ull*)&sW[B2A + d * 2];
#pragma unroll
            for (int n = 0; n < 4; n++) {
                float s0, s1, q0, q1;
                upk2(asum[n], s0, s1); upk2(asq[n], q0, q1);
                float mu = (s0 + s1) * (1.0f / 32.0f);
                float var = (q0 + q1) * (1.0f / 32.0f) - mu * mu;
                float rr = rsqrtf(var + 1e-5f);
                ull dmu = dupf(mu), drr = dupf(rr);
                ull o2a = b2, o2b = 0ull;
#pragma unroll
                for (int jp = 0; jp < 8; jp++) {
                    ull t2 = f2fma(dmu, sn[jp], aacc[n][jp]);
                    ull c2 = f2fma(drr, t2, bc[jp]);
                    float c0, c1; upk2(c2, c0, c1);
                    c0 = fmaxf(c0, 0.f); c1 = fmaxf(c1, 0.f);
                    o2a = f2fma(dupf(c0), w2[2 * jp], o2a);
                    o2b = f2fma(dupf(c1), w2[2 * jp + 1], o2b);
                }
                upk2(f2add(o2a, o2b), afn[n][0], afn[n][1]);
            }
        }
#pragma unroll
        for (int m = 0; m < 2; m++) { uf[m][0] = ufn[m][0]; uf[m][1] = ufn[m][1]; }
#pragma unroll
        for (int n = 0; n < 4; n++) { af[n][0] = afn[n][0]; af[n][1] = afn[n][1]; }
    }

    // ---------------- readout heads ----------------
    float td[8];
#pragma unroll
    for (int i = 0; i < 8; i++) {
        float acc = sW[RDB1 + i];
#pragma unroll
        for (int n = 0; n < 4; n++) acc = fmaf(af[n][1], sW[RDW1 + i * 4 + n], acc);
        td[i] = fmaxf(acc, 0.f);
    }
    float daux[4], sumd = 0.f;
#pragma unroll
    for (int j = 0; j < 4; j++) {
        float acc = sW[RDB2 + j];
#pragma unroll
        for (int i = 0; i < 8; i++) acc = fmaf(td[i], sW[RDW2 + j * 8 + i], acc);
        daux[j] = fmaxf(acc, 0.001f);
        sumd += daux[j];
    }
    float fd = BMAX_ / sumd;
    float sdelta[4], x[4];
    { float cum = 0.f;
#pragma unroll
      for (int n = 0; n < 4; n++) {
          sdelta[n] = daux[n] * fd;
          cum += sdelta[n];
          x[n] = cum + DMIN_ * (float)n - D_ * (float)(n + 1);
      } }

    float tp[8];
#pragma unroll
    for (int i = 0; i < 8; i++) {
        float acc = sW[RPB1 + i];
#pragma unroll
        for (int n = 0; n < 4; n++) acc = fmaf(af[n][0], sW[RPW1 + i * 4 + n], acc);
        tp[i] = fmaxf(acc, 0.f);
    }
    float paux[4], sump = 1e-6f;
#pragma unroll
    for (int j = 0; j < 4; j++) {
        float acc = sW[RPB2 + j];
#pragma unroll
        for (int i = 0; i < 8; i++) acc = fmaf(tp[i], sW[RPW2 + j * 8 + i], acc);
        paux[j] = fmaxf(acc, 0.001f);
        sump += paux[j];
    }
    float fp = PMAX_ / fmaxf(PMAX_, sump);

    ((float4*)out)[b] = make_float4(paux[0] * fp, paux[1] * fp, paux[2] * fp, paux[3] * fp);
    ((float4*)(out + 4 * (size_t)B))[b] = make_float4(sdelta[0], sdelta[1], sdelta[2], sdelta[3]);
    float* op = out + 8 * (size_t)B + (size_t)b * 12;
    ((float4*)op)[0] = make_float4(x[0], 0.f, HZ_, x[1]);
    ((float4*)op)[1] = make_float4(0.f, HZ_, x[2], 0.f);
    ((float4*)op)[2] = make_float4(HZ_, x[3], 0.f, HZ_);
}

extern "C" void kernel_launch(void* const* d_in, const int* in_sizes, int n_in,
                              void* d_out, int out_size) {
    Ptrs p;
    for (int i = 0; i < 28; i++) p.a[i] = (const float*)d_in[i];
    int B = in_sizes[0] / 4;
    int grid = (B + THREADS - 1) / THREADS;
    bgat_kernel<<<grid, THREADS>>>(p, (float*)d_out, B);
}